// round 7
// baseline (speedup 1.0000x reference)
#include <cuda_runtime.h>
#include <math.h>

#define BATCH 8
#define SEQ   512
#define CDIM  2048
#define NH    16
#define HD    128
#define MTOK  (BATCH*SEQ)      // 4096
#define F3    (3*CDIM)         // 6144

// Scratch (static device arrays; no allocation anywhere)
__device__ float g_qkv[MTOK * F3];
__device__ float g_q [BATCH*NH*SEQ*HD];   // [bh][t][d] scaled+tf32-rounded
__device__ float g_k [BATCH*NH*SEQ*HD];   // [bh][t][d] tf32-rounded
__device__ float g_vT[BATCH*NH*HD*SEQ];   // [bh][d][t] tf32-rounded (transposed)
__device__ float g_y [MTOK * CDIM];       // [b,t,C] tf32-rounded
__device__ float g_xr[MTOK * CDIM];
__device__ float g_w1[F3 * CDIM];
__device__ float g_w2[CDIM * CDIM];

// ---------------------------------------------------------------------------
__device__ __forceinline__ unsigned smem_u32(const void* p) {
    unsigned a;
    asm("{ .reg .u64 t; cvta.to.shared.u64 t, %1; cvt.u32.u64 %0, t; }"
        : "=r"(a) : "l"(p));
    return a;
}
__device__ __forceinline__ unsigned tf32r(unsigned x) {
    unsigned r;
    asm("cvt.rna.tf32.f32 %0, %1;" : "=r"(r) : "r"(x));
    return r;
}
__device__ __forceinline__ float tf32f(float x) {
    return __uint_as_float(tf32r(__float_as_uint(x)));
}
__device__ __forceinline__ void cp16(unsigned saddr, const void* gaddr) {
    asm volatile("cp.async.cg.shared.global [%0], [%1], 16;"
                 :: "r"(saddr), "l"(gaddr));
}
__device__ __forceinline__ void ldsm_x4(unsigned addr, unsigned& r0, unsigned& r1,
                                        unsigned& r2, unsigned& r3) {
    asm volatile("ldmatrix.sync.aligned.m8n8.x4.shared.b16 {%0,%1,%2,%3}, [%4];"
                 : "=r"(r0), "=r"(r1), "=r"(r2), "=r"(r3) : "r"(addr));
}
__device__ __forceinline__ void mma_tf32(float* c, const unsigned* a,
                                         unsigned b0, unsigned b1) {
    asm volatile(
        "mma.sync.aligned.m16n8k8.row.col.f32.tf32.tf32.f32 "
        "{%0,%1,%2,%3}, {%4,%5,%6,%7}, {%8,%9}, {%0,%1,%2,%3};"
        : "+f"(c[0]), "+f"(c[1]), "+f"(c[2]), "+f"(c[3])
        : "r"(a[0]), "r"(a[1]), "r"(a[2]), "r"(a[3]), "r"(b0), "r"(b1));
}

// tf32-round a float buffer (float4 grid-stride)
__global__ __launch_bounds__(256) void round_tf32_kernel(
    const float4* __restrict__ src, float4* __restrict__ dst, int n4)
{
    for (int i = blockIdx.x * blockDim.x + threadIdx.x; i < n4;
         i += gridDim.x * blockDim.x) {
        float4 v = src[i];
        uint4 u = *(uint4*)&v;
        u.x = tf32r(u.x); u.y = tf32r(u.y); u.z = tf32r(u.z); u.w = tf32r(u.w);
        dst[i] = *(float4*)&u;
    }
}

// ===========================================================================
// tf32 mma.sync GEMM: C[M,N] = A[M,K]*B[N,K]^T, 128x128x32 CTA tile,
// 128 threads = 4 warps, 64x64 warp tile, 3-stage cp.async pipeline.
// Stage indices are maintained incrementally (wrap on ++), no modulo.
// ===========================================================================
#define BM 128
#define BN 128
#define BK 32
#define LDK 36
#define TILE_B (BM * LDK * 4)               // 18432 B per matrix per stage
#define STAGE_B (2 * TILE_B)                // A+B per stage
#define GEMM_SMEM (3 * STAGE_B)             // 110592 B

__global__ __launch_bounds__(128) void gemm_tf32mma(
    const float* __restrict__ A, const float* __restrict__ B,
    float* __restrict__ C, int Nd, int Kd)
{
    extern __shared__ char smem[];
    const unsigned sbase = smem_u32(smem);
    const int tid  = threadIdx.x;
    const int lane = tid & 31;
    const int wid  = tid >> 5;
    const int warpM = wid >> 1;             // 0..1
    const int warpN = wid & 1;              // 0..1
    const int m0 = blockIdx.y * BM;
    const int n0 = blockIdx.x * BN;

    const int row_ld = tid >> 3;            // 0..15 (+ i*16)
    const int col16  = tid & 7;

    float acc[4][8][4];
#pragma unroll
    for (int a = 0; a < 4; a++)
#pragma unroll
        for (int b = 0; b < 8; b++)
#pragma unroll
            for (int c = 0; c < 4; c++) acc[a][b][c] = 0.0f;

    const int KT = Kd / BK;

    const float* Aptr = A + (size_t)(m0 + row_ld) * Kd + col16 * 4;
    const float* Bptr = B + (size_t)(n0 + row_ld) * Kd + col16 * 4;
    const size_t rstep = (size_t)16 * Kd;
    const unsigned ld_off = (unsigned)(row_ld * (LDK * 4) + col16 * 16);

    // prologue: stages 0,1
#pragma unroll
    for (int pk = 0; pk < 2; pk++) {
        unsigned sA = sbase + pk * STAGE_B + ld_off;
        unsigned sB = sA + TILE_B;
        const float* ap = Aptr + pk * BK;
        const float* bp = Bptr + pk * BK;
#pragma unroll
        for (int i = 0; i < 8; i++) {
            cp16(sA + i * (16 * LDK * 4), ap + i * rstep);
            cp16(sB + i * (16 * LDK * 4), bp + i * rstep);
        }
        asm volatile("cp.async.commit_group;" ::: "memory");
    }

    const unsigned aRowOff = (unsigned)((warpM * 64 + (lane & 15)) * (LDK * 4)
                                        + (lane >> 4) * 16);
    const unsigned bRowOff = (unsigned)((warpN * 64 + (lane & 15)) * (LDK * 4)
                                        + (lane >> 4) * 16);

    int pf_st = 2;     // stage to write next prefetch into (kt+2)
    int cs_st = 0;     // stage to consume this iteration (kt)

    for (int kt = 0; kt < KT; kt++) {
        if (kt < KT - 1)
            asm volatile("cp.async.wait_group 1;" ::: "memory");
        else
            asm volatile("cp.async.wait_group 0;" ::: "memory");
        __syncthreads();

        if (kt + 2 < KT) {
            unsigned sA = sbase + pf_st * STAGE_B + ld_off;
            unsigned sB = sA + TILE_B;
            const float* ap = Aptr + (kt + 2) * BK;
            const float* bp = Bptr + (kt + 2) * BK;
#pragma unroll
            for (int i = 0; i < 8; i++) {
                cp16(sA + i * (16 * LDK * 4), ap + i * rstep);
                cp16(sB + i * (16 * LDK * 4), bp + i * rstep);
            }
            asm volatile("cp.async.commit_group;" ::: "memory");
        }
        if (++pf_st == 3) pf_st = 0;

        const unsigned sAc = sbase + cs_st * STAGE_B;
        const unsigned sBc = sAc + TILE_B;
        if (++cs_st == 3) cs_st = 0;

#pragma unroll
        for (int kk = 0; kk < 4; kk++) {
            unsigned af[4][4];
#pragma unroll
            for (int mt = 0; mt < 4; mt++)
                ldsm_x4(sAc + aRowOff + mt * (16 * LDK * 4) + kk * 32,
                        af[mt][0], af[mt][1], af[mt][2], af[mt][3]);
            unsigned bf[8][2];
#pragma unroll
            for (int ntp = 0; ntp < 4; ntp++) {
                unsigned r0, r1, r2, r3;
                ldsm_x4(sBc + bRowOff + ntp * (16 * LDK * 4) + kk * 32,
                        r0, r1, r2, r3);
                bf[2 * ntp][0] = r0;     bf[2 * ntp][1] = r2;
                bf[2 * ntp + 1][0] = r1; bf[2 * ntp + 1][1] = r3;
            }
#pragma unroll
            for (int mt = 0; mt < 4; mt++)
#pragma unroll
                for (int nt = 0; nt < 8; nt++)
                    mma_tf32(acc[mt][nt], af[mt], bf[nt][0], bf[nt][1]);
        }
    }

    const int rBase = m0 + warpM * 64 + (lane >> 2);
    const int cBase = n0 + warpN * 64 + (lane & 3) * 2;
#pragma unroll
    for (int mt = 0; mt < 4; mt++)
#pragma unroll
        for (int nt = 0; nt < 8; nt++) {
            float* p0 = C + (size_t)(rBase + mt * 16) * Nd + cBase + nt * 8;
            float* p1 = C + (size_t)(rBase + mt * 16 + 8) * Nd + cBase + nt * 8;
            *(float2*)p0 = make_float2(acc[mt][nt][0], acc[mt][nt][1]);
            *(float2*)p1 = make_float2(acc[mt][nt][2], acc[mt][nt][3]);
        }
}

// ---------------------------------------------------------------------------
// RoPE + split. Writes q (scaled, tf32), k (tf32) in [bh][t][d], and
// v TRANSPOSED (tf32) in [bh][d][t] via smem transpose.
// ---------------------------------------------------------------------------
__global__ __launch_bounds__(128) void rope_kernel()
{
    __shared__ float vsm[128][33];
    const int bh = blockIdx.y;
    const int b = bh >> 4, h = bh & 15;
    const int t0 = blockIdx.x * 32;
    const int d = threadIdx.x;

    float freq = 0.0f;
    if (d < 16) freq = __powf(10000.0f, -(float)(d & 7) * 0.125f);

    for (int tl = 0; tl < 32; tl++) {
        int t = t0 + tl;
        const float* src = g_qkv + (size_t)(b * SEQ + t) * F3 + h * HD;
        float qv = src[d];
        float kv = src[CDIM + d];
        float vv = src[2 * CDIM + d];
        if (d < 16) {
            float s, c;
            __sincosf((float)t * freq, &s, &c);
            if (d < 8) {
                qv = qv * c - src[d + 8] * s;
                kv = kv * c - src[CDIM + d + 8] * s;
            } else {
                qv = qv * c + src[d - 8] * s;
                kv = kv * c + src[CDIM + d - 8] * s;
            }
        }
        size_t dst = ((size_t)bh * SEQ + t) * HD + d;
        g_q[dst] = tf32f(qv * 0.08838834764831845f);
        g_k[dst] = tf32f(kv);
        vsm[d][tl] = tf32f(vv);
    }
    __syncthreads();
#pragma unroll
    for (int i = 0; i < 8; i++) {
        int row = (threadIdx.x >> 3) + i * 16;
        int c = (threadIdx.x & 7) * 4;
        float4 v = make_float4(vsm[row][c], vsm[row][c + 1],
                               vsm[row][c + 2], vsm[row][c + 3]);
        *(float4*)(g_vT + ((size_t)bh * HD + row) * SEQ + t0 + c) = v;
    }
}

// ===========================================================================
// Flash attention with tf32 mma: CTA = 64 queries x 1 (b,h), Bc=32 keys.
// ===========================================================================
#define AK_PITCH 528
#define AV_PITCH 144
#define OFF_K0   0
#define OFF_K1   16896
#define OFF_V0   33792
#define OFF_V1   52224
#define OFF_P    70656
#define ATTN_SMEM 79872

__global__ __launch_bounds__(128, 2) void fattn_kernel()
{
    extern __shared__ char smem[];
    const unsigned sb = smem_u32(smem);
    const int bh = blockIdx.y;
    const int qt = blockIdx.x;
    const int q0 = qt * 64;
    const int jmax = 2 * qt + 1;
    const int tid = threadIdx.x;
    const int lane = tid & 31;
    const int wq = tid >> 5;

    {
        const float* qg = g_q + ((size_t)bh * SEQ + q0) * HD;
#pragma unroll
        for (int i = 0; i < 16; i++) {
            int id = tid + i * 128;
            int row = id >> 5, c16 = id & 31;
            cp16(sb + row * AK_PITCH + c16 * 16, qg + row * HD + c16 * 4);
        }
        asm volatile("cp.async.commit_group;" ::: "memory");
        asm volatile("cp.async.wait_group 0;" ::: "memory");
        __syncthreads();
    }
    unsigned qf[16][4];
    {
        unsigned qaddr = sb + (wq * 16 + (lane & 15)) * AK_PITCH + (lane >> 4) * 16;
#pragma unroll
        for (int kk = 0; kk < 16; kk++)
            ldsm_x4(qaddr + kk * 32, qf[kk][0], qf[kk][1], qf[kk][2], qf[kk][3]);
    }
    __syncthreads();

    float m1 = -1e30f, m2 = -1e30f, l1 = 0.0f, l2 = 0.0f;
    float oacc[16][4];
#pragma unroll
    for (int nt = 0; nt < 16; nt++)
#pragma unroll
        for (int c = 0; c < 4; c++) oacc[nt][c] = 0.0f;

    auto load_tile = [&](int j) {
        unsigned kb = sb + ((j & 1) ? OFF_K1 : OFF_K0);
        unsigned vb = sb + ((j & 1) ? OFF_V1 : OFF_V0);
        const float* kg = g_k + ((size_t)bh * SEQ + j * 32) * HD;
        const float* vg = g_vT + (size_t)bh * HD * SEQ + j * 32;
#pragma unroll
        for (int i = 0; i < 8; i++) {
            int id = tid + i * 128;
            int kr = id >> 5, kc = id & 31;
            cp16(kb + kr * AK_PITCH + kc * 16, kg + kr * HD + kc * 4);
            int vr = id >> 3, vc = id & 7;
            cp16(vb + vr * AV_PITCH + vc * 16, vg + (size_t)vr * SEQ + vc * 4);
        }
        asm volatile("cp.async.commit_group;" ::: "memory");
    };

    load_tile(0);

    const int rowg1 = q0 + wq * 16 + (lane >> 2);

    for (int j = 0; j <= jmax; j++) {
        asm volatile("cp.async.wait_group 0;" ::: "memory");
        __syncthreads();
        if (j < jmax) load_tile(j + 1);

        float sacc[4][4];
#pragma unroll
        for (int nt = 0; nt < 4; nt++)
#pragma unroll
            for (int c = 0; c < 4; c++) sacc[nt][c] = 0.0f;

        const unsigned kbase = sb + ((j & 1) ? OFF_K1 : OFF_K0);
        const unsigned half16 = (unsigned)((lane >> 4) * 16);
#pragma unroll
        for (int kk = 0; kk < 16; kk++) {
            unsigned bf[4][2];
#pragma unroll
            for (int ntp = 0; ntp < 2; ntp++) {
                unsigned r0, r1, r2, r3;
                ldsm_x4(kbase + (ntp * 16 + (lane & 15)) * AK_PITCH + kk * 32 + half16,
                        r0, r1, r2, r3);
                bf[2 * ntp][0] = r0;     bf[2 * ntp][1] = r2;
                bf[2 * ntp + 1][0] = r1; bf[2 * ntp + 1][1] = r3;
            }
#pragma unroll
            for (int nt = 0; nt < 4; nt++)
                mma_tf32(sacc[nt], qf[kk], bf[nt][0], bf[nt][1]);
        }

        if (j * 32 + 31 > q0 + wq * 16) {
#pragma unroll
            for (int nt = 0; nt < 4; nt++) {
                int colb = j * 32 + nt * 8 + (lane & 3) * 2;
                if (colb     > rowg1)     sacc[nt][0] = -1e30f;
                if (colb + 1 > rowg1)     sacc[nt][1] = -1e30f;
                if (colb     > rowg1 + 8) sacc[nt][2] = -1e30f;
                if (colb + 1 > rowg1 + 8) sacc[nt][3] = -1e30f;
            }
        }

        float tm1 = -1e30f, tm2 = -1e30f;
#pragma unroll
        for (int nt = 0; nt < 4; nt++) {
            tm1 = fmaxf(tm1, fmaxf(sacc[nt][0], sacc[nt][1]));
            tm2 = fmaxf(tm2, fmaxf(sacc[nt][2], sacc[nt][3]));
        }
        tm1 = fmaxf(tm1, __shfl_xor_sync(0xffffffffu, tm1, 1));
        tm1 = fmaxf(tm1, __shfl_xor_sync(0xffffffffu, tm1, 2));
        tm2 = fmaxf(tm2, __shfl_xor_sync(0xffffffffu, tm2, 1));
        tm2 = fmaxf(tm2, __shfl_xor_sync(0xffffffffu, tm2, 2));

        float m1n = fmaxf(m1, tm1), m2n = fmaxf(m2, tm2);
        float corr1 = __expf(m1 - m1n), corr2 = __expf(m2 - m2n);
        m1 = m1n; m2 = m2n;

        float rs1 = 0.0f, rs2 = 0.0f;
#pragma unroll
        for (int nt = 0; nt < 4; nt++) {
            sacc[nt][0] = __expf(sacc[nt][0] - m1n);
            sacc[nt][1] = __expf(sacc[nt][1] - m1n);
            sacc[nt][2] = __expf(sacc[nt][2] - m2n);
            sacc[nt][3] = __expf(sacc[nt][3] - m2n);
            rs1 += sacc[nt][0] + sacc[nt][1];
            rs2 += sacc[nt][2] + sacc[nt][3];
        }
        rs1 += __shfl_xor_sync(0xffffffffu, rs1, 1);
        rs1 += __shfl_xor_sync(0xffffffffu, rs1, 2);
        rs2 += __shfl_xor_sync(0xffffffffu, rs2, 1);
        rs2 += __shfl_xor_sync(0xffffffffu, rs2, 2);
        l1 = l1 * corr1 + rs1;
        l2 = l2 * corr2 + rs2;

#pragma unroll
        for (int nt = 0; nt < 16; nt++) {
            oacc[nt][0] *= corr1; oacc[nt][1] *= corr1;
            oacc[nt][2] *= corr2; oacc[nt][3] *= corr2;
        }

        {
            int pr1 = wq * 16 + (lane >> 2);
            int pc = (lane & 3) * 2;
#pragma unroll
            for (int nt = 0; nt < 4; nt++) {
                *(float2*)(smem + OFF_P + (pr1 * 36 + nt * 8 + pc) * 4) =
                    make_float2(tf32f(sacc[nt][0]), tf32f(sacc[nt][1]));
                *(float2*)(smem + OFF_P + ((pr1 + 8) * 36 + nt * 8 + pc) * 4) =
                    make_float2(tf32f(sacc[nt][2]), tf32f(sacc[nt][3]));
            }
        }
        __syncthreads();

        const unsigned vbase = sb + ((j & 1) ? OFF_V1 : OFF_V0);
        const unsigned paddr = sb + OFF_P + (wq * 16 + (lane & 15)) * AV_PITCH + half16;
#pragma unroll
        for (int kkc = 0; kkc < 4; kkc++) {
            unsigned pf[4];
            ldsm_x4(paddr + kkc * 32, pf[0], pf[1], pf[2], pf[3]);
#pragma unroll
            for (int ntp = 0; ntp < 8; ntp++) {
                unsigned r0, r1, r2, r3;
                ldsm_x4(vbase + (ntp * 16 + (lane & 15)) * AV_PITCH + kkc * 32 + half16,
                        r0, r1, r2, r3);
                mma_tf32(oacc[2 * ntp],     pf, r0, r2);
                mma_tf32(oacc[2 * ntp + 1], pf, r1, r3);
            }
        }
        __syncthreads();
    }

    float inv1 = 1.0f / l1, inv2 = 1.0f / l2;
    int b = bh >> 4, h = bh & 15;
    int row1 = q0 + wq * 16 + (lane >> 2);
#pragma unroll
    for (int nt = 0; nt < 16; nt++) {
        int d = nt * 8 + (lane & 3) * 2;
        float* p0 = g_y + (size_t)(b * SEQ + row1) * CDIM + h * HD + d;
        float* p1 = g_y + (size_t)(b * SEQ + row1 + 8) * CDIM + h * HD + d;
        *(float2*)p0 = make_float2(tf32f(oacc[nt][0] * inv1), tf32f(oacc[nt][1] * inv1));
        *(float2*)p1 = make_float2(tf32f(oacc[nt][2] * inv2), tf32f(oacc[nt][3] * inv2));
    }
}

// ---------------------------------------------------------------------------
extern "C" void kernel_launch(void* const* d_in, const int* in_sizes, int n_in,
                              void* d_out, int out_size)
{
    (void)in_sizes; (void)n_in; (void)out_size;
    const float* x    = (const float*)d_in[0];
    const float* Wqkv = (const float*)d_in[1];
    const float* Wout = (const float*)d_in[2];
    float* out = (float*)d_out;

    float *qkv_p, *y_p, *xr_p, *w1_p, *w2_p;
    cudaGetSymbolAddress((void**)&qkv_p, g_qkv);
    cudaGetSymbolAddress((void**)&y_p,  g_y);
    cudaGetSymbolAddress((void**)&xr_p, g_xr);
    cudaGetSymbolAddress((void**)&w1_p, g_w1);
    cudaGetSymbolAddress((void**)&w2_p, g_w2);

    cudaFuncSetAttribute(gemm_tf32mma,
                         cudaFuncAttributeMaxDynamicSharedMemorySize, GEMM_SMEM);
    cudaFuncSetAttribute(fattn_kernel,
                         cudaFuncAttributeMaxDynamicSharedMemorySize, ATTN_SMEM);

    // 0) tf32-round GEMM inputs
    round_tf32_kernel<<<1184, 256>>>((const float4*)x,    (float4*)xr_p, MTOK * CDIM / 4);
    round_tf32_kernel<<<1184, 256>>>((const float4*)Wqkv, (float4*)w1_p, F3 * CDIM / 4);
    round_tf32_kernel<<<1184, 256>>>((const float4*)Wout, (float4*)w2_p, CDIM * CDIM / 4);

    // 1) qkv = x @ Wqkv^T
    gemm_tf32mma<<<dim3(F3 / BN, MTOK / BM), 128, GEMM_SMEM>>>(xr_p, w1_p, qkv_p, F3, CDIM);

    // 2) RoPE + split + V transpose
    rope_kernel<<<dim3(SEQ / 32, BATCH * NH), 128>>>();

    // 3) flash attention (tf32 mma) -> y
    fattn_kernel<<<dim3(SEQ / 64, BATCH * NH), 128, ATTN_SMEM>>>();

    // 4) out = y @ Wout^T
    gemm_tf32mma<<<dim3(CDIM / BN, MTOK / BM), 128, GEMM_SMEM>>>(y_p, w2_p, out, CDIM, CDIM);
}

// round 8
// speedup vs baseline: 1.0381x; 1.0381x over previous
#include <cuda_runtime.h>
#include <math.h>

#define BATCH 8
#define SEQ   512
#define CDIM  2048
#define NH    16
#define HD    128
#define MTOK  (BATCH*SEQ)      // 4096
#define F3    (3*CDIM)         // 6144

// Scratch (static device arrays; no allocation anywhere)
__device__ float g_qkv[MTOK * F3];
__device__ float g_q [BATCH*NH*SEQ*HD];   // [bh][t][d] scaled+tf32-rounded
__device__ float g_k [BATCH*NH*SEQ*HD];   // [bh][t][d] tf32-rounded
__device__ float g_vT[BATCH*NH*HD*SEQ];   // [bh][d][t] tf32-rounded (transposed)
__device__ float g_y [MTOK * CDIM];       // [b,t,C] tf32-rounded
__device__ float g_xr[MTOK * CDIM];
__device__ float g_w1[F3 * CDIM];
__device__ float g_w2[CDIM * CDIM];

// ---------------------------------------------------------------------------
__device__ __forceinline__ unsigned smem_u32(const void* p) {
    unsigned a;
    asm("{ .reg .u64 t; cvta.to.shared.u64 t, %1; cvt.u32.u64 %0, t; }"
        : "=r"(a) : "l"(p));
    return a;
}
__device__ __forceinline__ unsigned tf32r(unsigned x) {
    unsigned r;
    asm("cvt.rna.tf32.f32 %0, %1;" : "=r"(r) : "r"(x));
    return r;
}
__device__ __forceinline__ float tf32f(float x) {
    return __uint_as_float(tf32r(__float_as_uint(x)));
}
__device__ __forceinline__ void cp16(unsigned saddr, const void* gaddr) {
    asm volatile("cp.async.cg.shared.global [%0], [%1], 16;"
                 :: "r"(saddr), "l"(gaddr));
}
__device__ __forceinline__ void ldsm_x4(unsigned addr, unsigned& r0, unsigned& r1,
                                        unsigned& r2, unsigned& r3) {
    asm volatile("ldmatrix.sync.aligned.m8n8.x4.shared.b16 {%0,%1,%2,%3}, [%4];"
                 : "=r"(r0), "=r"(r1), "=r"(r2), "=r"(r3) : "r"(addr));
}
__device__ __forceinline__ void mma_tf32(float* c, const unsigned* a,
                                         unsigned b0, unsigned b1) {
    asm volatile(
        "mma.sync.aligned.m16n8k8.row.col.f32.tf32.tf32.f32 "
        "{%0,%1,%2,%3}, {%4,%5,%6,%7}, {%8,%9}, {%0,%1,%2,%3};"
        : "+f"(c[0]), "+f"(c[1]), "+f"(c[2]), "+f"(c[3])
        : "r"(a[0]), "r"(a[1]), "r"(a[2]), "r"(a[3]), "r"(b0), "r"(b1));
}

// tf32-round a float buffer (float4 grid-stride)
__global__ __launch_bounds__(256) void round_tf32_kernel(
    const float4* __restrict__ src, float4* __restrict__ dst, int n4)
{
    for (int i = blockIdx.x * blockDim.x + threadIdx.x; i < n4;
         i += gridDim.x * blockDim.x) {
        float4 v = src[i];
        uint4 u = *(uint4*)&v;
        u.x = tf32r(u.x); u.y = tf32r(u.y); u.z = tf32r(u.z); u.w = tf32r(u.w);
        dst[i] = *(float4*)&u;
    }
}

// ===========================================================================
// tf32 mma.sync GEMM: C[M,N] = A[M,K]*B[N,K]^T, 128x128x32 CTA tile,
// 256 threads = 8 warps (2x4), warp tile 64x32.  2-stage cp.async with
// prefetch-before-wait (round-3 structure, best measured), PLUS fragment
// double-buffering across kk steps so ldmatrix latency hides under mma issue.
// ===========================================================================
#define BM 128
#define BN 128
#define BK 32
#define LDK 36
#define TILE_B (BM * LDK * 4)              // 18432 bytes per matrix buffer
#define GEMM_SMEM (4 * TILE_B)             // A0 A1 B0 B1

__global__ __launch_bounds__(256, 2) void gemm_tf32mma(
    const float* __restrict__ A, const float* __restrict__ B,
    float* __restrict__ C, int Nd, int Kd)
{
    extern __shared__ char smem[];
    const unsigned sbase = smem_u32(smem);
    const int tid  = threadIdx.x;
    const int lane = tid & 31;
    const int wid  = tid >> 5;
    const int warpM = wid >> 2;            // 0..1
    const int warpN = wid & 3;             // 0..3
    const int m0 = blockIdx.y * BM;
    const int n0 = blockIdx.x * BN;

    const unsigned sA[2] = { sbase, sbase + TILE_B };
    const unsigned sB[2] = { sbase + 2 * TILE_B, sbase + 3 * TILE_B };

    const int row_ld  = tid >> 3;
    const int col16   = tid & 7;

    float acc[4][4][4];
#pragma unroll
    for (int a = 0; a < 4; a++)
#pragma unroll
        for (int b = 0; b < 4; b++)
#pragma unroll
            for (int c = 0; c < 4; c++) acc[a][b][c] = 0.0f;

    const int KT = Kd / BK;

    // ---- prologue: load tile 0
    {
        const float* Ab = A + (size_t)m0 * Kd;
        const float* Bb = B + (size_t)n0 * Kd;
#pragma unroll
        for (int i = 0; i < 4; i++) {
            int r = row_ld + i * 32;
            cp16(sA[0] + (unsigned)(r * (LDK * 4) + col16 * 16),
                 Ab + (size_t)r * Kd + col16 * 4);
            cp16(sB[0] + (unsigned)(r * (LDK * 4) + col16 * 16),
                 Bb + (size_t)r * Kd + col16 * 4);
        }
        asm volatile("cp.async.commit_group;" ::: "memory");
    }

    const unsigned aRowOff = (unsigned)((warpM * 64 + (lane & 15)) * (LDK * 4)
                                        + (lane >> 4) * 16);
    const unsigned bRowOff = (unsigned)((warpN * 32 + (lane & 15)) * (LDK * 4)
                                        + (lane >> 4) * 16);

    for (int kt = 0; kt < KT; kt++) {
        const int cur = kt & 1;
        if (kt + 1 < KT) {
            const int nxt = cur ^ 1;
            const float* Ab = A + (size_t)m0 * Kd + (kt + 1) * BK;
            const float* Bb = B + (size_t)n0 * Kd + (kt + 1) * BK;
#pragma unroll
            for (int i = 0; i < 4; i++) {
                int r = row_ld + i * 32;
                cp16(sA[nxt] + (unsigned)(r * (LDK * 4) + col16 * 16),
                     Ab + (size_t)r * Kd + col16 * 4);
                cp16(sB[nxt] + (unsigned)(r * (LDK * 4) + col16 * 16),
                     Bb + (size_t)r * Kd + col16 * 4);
            }
            asm volatile("cp.async.commit_group;" ::: "memory");
            asm volatile("cp.async.wait_group 1;" ::: "memory");
        } else {
            asm volatile("cp.async.wait_group 0;" ::: "memory");
        }
        __syncthreads();

        const unsigned aBase = sA[cur] + aRowOff;
        const unsigned bBase = sB[cur] + bRowOff;

        // fragment double buffers (kk-pipelined)
        unsigned af[2][4][4];
        unsigned bf[2][4][2];

        // load kk = 0 into buffer 0
#pragma unroll
        for (int mt = 0; mt < 4; mt++)
            ldsm_x4(aBase + mt * (16 * LDK * 4),
                    af[0][mt][0], af[0][mt][1], af[0][mt][2], af[0][mt][3]);
#pragma unroll
        for (int ntp = 0; ntp < 2; ntp++) {
            unsigned r0, r1, r2, r3;
            ldsm_x4(bBase + ntp * (16 * LDK * 4), r0, r1, r2, r3);
            bf[0][2 * ntp][0] = r0;     bf[0][2 * ntp][1] = r2;
            bf[0][2 * ntp + 1][0] = r1; bf[0][2 * ntp + 1][1] = r3;
        }

#pragma unroll
        for (int kk = 0; kk < 4; kk++) {
            const int cb = kk & 1;
            const int nb = cb ^ 1;
            if (kk < 3) {
                // prefetch fragments for kk+1 while mma of kk issues
#pragma unroll
                for (int mt = 0; mt < 4; mt++)
                    ldsm_x4(aBase + mt * (16 * LDK * 4) + (kk + 1) * 32,
                            af[nb][mt][0], af[nb][mt][1],
                            af[nb][mt][2], af[nb][mt][3]);
#pragma unroll
                for (int ntp = 0; ntp < 2; ntp++) {
                    unsigned r0, r1, r2, r3;
                    ldsm_x4(bBase + ntp * (16 * LDK * 4) + (kk + 1) * 32,
                            r0, r1, r2, r3);
                    bf[nb][2 * ntp][0] = r0;     bf[nb][2 * ntp][1] = r2;
                    bf[nb][2 * ntp + 1][0] = r1; bf[nb][2 * ntp + 1][1] = r3;
                }
            }
#pragma unroll
            for (int mt = 0; mt < 4; mt++)
#pragma unroll
                for (int nt = 0; nt < 4; nt++)
                    mma_tf32(acc[mt][nt], af[cb][mt], bf[cb][nt][0], bf[cb][nt][1]);
        }
        __syncthreads();
    }

    // Epilogue: direct float2 stores
    const int rBase = m0 + warpM * 64 + (lane >> 2);
    const int cBase = n0 + warpN * 32 + (lane & 3) * 2;
#pragma unroll
    for (int mt = 0; mt < 4; mt++)
#pragma unroll
        for (int nt = 0; nt < 4; nt++) {
            float* p0 = C + (size_t)(rBase + mt * 16) * Nd + cBase + nt * 8;
            float* p1 = C + (size_t)(rBase + mt * 16 + 8) * Nd + cBase + nt * 8;
            *(float2*)p0 = make_float2(acc[mt][nt][0], acc[mt][nt][1]);
            *(float2*)p1 = make_float2(acc[mt][nt][2], acc[mt][nt][3]);
        }
}

// ---------------------------------------------------------------------------
// RoPE + split. Writes q (scaled, tf32), k (tf32) in [bh][t][d], and
// v TRANSPOSED (tf32) in [bh][d][t] via smem transpose.
// ---------------------------------------------------------------------------
__global__ __launch_bounds__(128) void rope_kernel()
{
    __shared__ float vsm[128][33];
    const int bh = blockIdx.y;
    const int b = bh >> 4, h = bh & 15;
    const int t0 = blockIdx.x * 32;
    const int d = threadIdx.x;

    float freq = 0.0f;
    if (d < 16) freq = __powf(10000.0f, -(float)(d & 7) * 0.125f);

    for (int tl = 0; tl < 32; tl++) {
        int t = t0 + tl;
        const float* src = g_qkv + (size_t)(b * SEQ + t) * F3 + h * HD;
        float qv = src[d];
        float kv = src[CDIM + d];
        float vv = src[2 * CDIM + d];
        if (d < 16) {
            float s, c;
            __sincosf((float)t * freq, &s, &c);
            if (d < 8) {
                qv = qv * c - src[d + 8] * s;
                kv = kv * c - src[CDIM + d + 8] * s;
            } else {
                qv = qv * c + src[d - 8] * s;
                kv = kv * c + src[CDIM + d - 8] * s;
            }
        }
        size_t dst = ((size_t)bh * SEQ + t) * HD + d;
        g_q[dst] = tf32f(qv * 0.08838834764831845f);
        g_k[dst] = tf32f(kv);
        vsm[d][tl] = tf32f(vv);
    }
    __syncthreads();
#pragma unroll
    for (int i = 0; i < 8; i++) {
        int row = (threadIdx.x >> 3) + i * 16;
        int c = (threadIdx.x & 7) * 4;
        float4 v = make_float4(vsm[row][c], vsm[row][c + 1],
                               vsm[row][c + 2], vsm[row][c + 3]);
        *(float4*)(g_vT + ((size_t)bh * HD + row) * SEQ + t0 + c) = v;
    }
}

// ===========================================================================
// Flash attention with tf32 mma: CTA = 64 queries x 1 (b,h), Bc=32 keys.
// ===========================================================================
#define AK_PITCH 528
#define AV_PITCH 144
#define OFF_K0   0
#define OFF_K1   16896
#define OFF_V0   33792
#define OFF_V1   52224
#define OFF_P    70656
#define ATTN_SMEM 79872

__global__ __launch_bounds__(128, 2) void fattn_kernel()
{
    extern __shared__ char smem[];
    const unsigned sb = smem_u32(smem);
    const int bh = blockIdx.y;
    const int qt = blockIdx.x;
    const int q0 = qt * 64;
    const int jmax = 2 * qt + 1;
    const int tid = threadIdx.x;
    const int lane = tid & 31;
    const int wq = tid >> 5;

    {
        const float* qg = g_q + ((size_t)bh * SEQ + q0) * HD;
#pragma unroll
        for (int i = 0; i < 16; i++) {
            int id = tid + i * 128;
            int row = id >> 5, c16 = id & 31;
            cp16(sb + row * AK_PITCH + c16 * 16, qg + row * HD + c16 * 4);
        }
        asm volatile("cp.async.commit_group;" ::: "memory");
        asm volatile("cp.async.wait_group 0;" ::: "memory");
        __syncthreads();
    }
    unsigned qf[16][4];
    {
        unsigned qaddr = sb + (wq * 16 + (lane & 15)) * AK_PITCH + (lane >> 4) * 16;
#pragma unroll
        for (int kk = 0; kk < 16; kk++)
            ldsm_x4(qaddr + kk * 32, qf[kk][0], qf[kk][1], qf[kk][2], qf[kk][3]);
    }
    __syncthreads();

    float m1 = -1e30f, m2 = -1e30f, l1 = 0.0f, l2 = 0.0f;
    float oacc[16][4];
#pragma unroll
    for (int nt = 0; nt < 16; nt++)
#pragma unroll
        for (int c = 0; c < 4; c++) oacc[nt][c] = 0.0f;

    auto load_tile = [&](int j) {
        unsigned kb = sb + ((j & 1) ? OFF_K1 : OFF_K0);
        unsigned vb = sb + ((j & 1) ? OFF_V1 : OFF_V0);
        const float* kg = g_k + ((size_t)bh * SEQ + j * 32) * HD;
        const float* vg = g_vT + (size_t)bh * HD * SEQ + j * 32;
#pragma unroll
        for (int i = 0; i < 8; i++) {
            int id = tid + i * 128;
            int kr = id >> 5, kc = id & 31;
            cp16(kb + kr * AK_PITCH + kc * 16, kg + kr * HD + kc * 4);
            int vr = id >> 3, vc = id & 7;
            cp16(vb + vr * AV_PITCH + vc * 16, vg + (size_t)vr * SEQ + vc * 4);
        }
        asm volatile("cp.async.commit_group;" ::: "memory");
    };

    load_tile(0);

    const int rowg1 = q0 + wq * 16 + (lane >> 2);

    for (int j = 0; j <= jmax; j++) {
        asm volatile("cp.async.wait_group 0;" ::: "memory");
        __syncthreads();
        if (j < jmax) load_tile(j + 1);

        float sacc[4][4];
#pragma unroll
        for (int nt = 0; nt < 4; nt++)
#pragma unroll
            for (int c = 0; c < 4; c++) sacc[nt][c] = 0.0f;

        const unsigned kbase = sb + ((j & 1) ? OFF_K1 : OFF_K0);
        const unsigned half16 = (unsigned)((lane >> 4) * 16);
#pragma unroll
        for (int kk = 0; kk < 16; kk++) {
            unsigned bf[4][2];
#pragma unroll
            for (int ntp = 0; ntp < 2; ntp++) {
                unsigned r0, r1, r2, r3;
                ldsm_x4(kbase + (ntp * 16 + (lane & 15)) * AK_PITCH + kk * 32 + half16,
                        r0, r1, r2, r3);
                bf[2 * ntp][0] = r0;     bf[2 * ntp][1] = r2;
                bf[2 * ntp + 1][0] = r1; bf[2 * ntp + 1][1] = r3;
            }
#pragma unroll
            for (int nt = 0; nt < 4; nt++)
                mma_tf32(sacc[nt], qf[kk], bf[nt][0], bf[nt][1]);
        }

        if (j * 32 + 31 > q0 + wq * 16) {
#pragma unroll
            for (int nt = 0; nt < 4; nt++) {
                int colb = j * 32 + nt * 8 + (lane & 3) * 2;
                if (colb     > rowg1)     sacc[nt][0] = -1e30f;
                if (colb + 1 > rowg1)     sacc[nt][1] = -1e30f;
                if (colb     > rowg1 + 8) sacc[nt][2] = -1e30f;
                if (colb + 1 > rowg1 + 8) sacc[nt][3] = -1e30f;
            }
        }

        float tm1 = -1e30f, tm2 = -1e30f;
#pragma unroll
        for (int nt = 0; nt < 4; nt++) {
            tm1 = fmaxf(tm1, fmaxf(sacc[nt][0], sacc[nt][1]));
            tm2 = fmaxf(tm2, fmaxf(sacc[nt][2], sacc[nt][3]));
        }
        tm1 = fmaxf(tm1, __shfl_xor_sync(0xffffffffu, tm1, 1));
        tm1 = fmaxf(tm1, __shfl_xor_sync(0xffffffffu, tm1, 2));
        tm2 = fmaxf(tm2, __shfl_xor_sync(0xffffffffu, tm2, 1));
        tm2 = fmaxf(tm2, __shfl_xor_sync(0xffffffffu, tm2, 2));

        float m1n = fmaxf(m1, tm1), m2n = fmaxf(m2, tm2);
        float corr1 = __expf(m1 - m1n), corr2 = __expf(m2 - m2n);
        m1 = m1n; m2 = m2n;

        float rs1 = 0.0f, rs2 = 0.0f;
#pragma unroll
        for (int nt = 0; nt < 4; nt++) {
            sacc[nt][0] = __expf(sacc[nt][0] - m1n);
            sacc[nt][1] = __expf(sacc[nt][1] - m1n);
            sacc[nt][2] = __expf(sacc[nt][2] - m2n);
            sacc[nt][3] = __expf(sacc[nt][3] - m2n);
            rs1 += sacc[nt][0] + sacc[nt][1];
            rs2 += sacc[nt][2] + sacc[nt][3];
        }
        rs1 += __shfl_xor_sync(0xffffffffu, rs1, 1);
        rs1 += __shfl_xor_sync(0xffffffffu, rs1, 2);
        rs2 += __shfl_xor_sync(0xffffffffu, rs2, 1);
        rs2 += __shfl_xor_sync(0xffffffffu, rs2, 2);
        l1 = l1 * corr1 + rs1;
        l2 = l2 * corr2 + rs2;

#pragma unroll
        for (int nt = 0; nt < 16; nt++) {
            oacc[nt][0] *= corr1; oacc[nt][1] *= corr1;
            oacc[nt][2] *= corr2; oacc[nt][3] *= corr2;
        }

        {
            int pr1 = wq * 16 + (lane >> 2);
            int pc = (lane & 3) * 2;
#pragma unroll
            for (int nt = 0; nt < 4; nt++) {
                *(float2*)(smem + OFF_P + (pr1 * 36 + nt * 8 + pc) * 4) =
                    make_float2(tf32f(sacc[nt][0]), tf32f(sacc[nt][1]));
                *(float2*)(smem + OFF_P + ((pr1 + 8) * 36 + nt * 8 + pc) * 4) =
                    make_float2(tf32f(sacc[nt][2]), tf32f(sacc[nt][3]));
            }
        }
        __syncthreads();

        const unsigned vbase = sb + ((j & 1) ? OFF_V1 : OFF_V0);
        const unsigned paddr = sb + OFF_P + (wq * 16 + (lane & 15)) * AV_PITCH + half16;
#pragma unroll
        for (int kkc = 0; kkc < 4; kkc++) {
            unsigned pf[4];
            ldsm_x4(paddr + kkc * 32, pf[0], pf[1], pf[2], pf[3]);
#pragma unroll
            for (int ntp = 0; ntp < 8; ntp++) {
                unsigned r0, r1, r2, r3;
                ldsm_x4(vbase + (ntp * 16 + (lane & 15)) * AV_PITCH + kkc * 32 + half16,
                        r0, r1, r2, r3);
                mma_tf32(oacc[2 * ntp],     pf, r0, r2);
                mma_tf32(oacc[2 * ntp + 1], pf, r1, r3);
            }
        }
        __syncthreads();
    }

    float inv1 = 1.0f / l1, inv2 = 1.0f / l2;
    int b = bh >> 4, h = bh & 15;
    int row1 = q0 + wq * 16 + (lane >> 2);
#pragma unroll
    for (int nt = 0; nt < 16; nt++) {
        int d = nt * 8 + (lane & 3) * 2;
        float* p0 = g_y + (size_t)(b * SEQ + row1) * CDIM + h * HD + d;
        float* p1 = g_y + (size_t)(b * SEQ + row1 + 8) * CDIM + h * HD + d;
        *(float2*)p0 = make_float2(tf32f(oacc[nt][0] * inv1), tf32f(oacc[nt][1] * inv1));
        *(float2*)p1 = make_float2(tf32f(oacc[nt][2] * inv2), tf32f(oacc[nt][3] * inv2));
    }
}

// ---------------------------------------------------------------------------
extern "C" void kernel_launch(void* const* d_in, const int* in_sizes, int n_in,
                              void* d_out, int out_size)
{
    (void)in_sizes; (void)n_in; (void)out_size;
    const float* x    = (const float*)d_in[0];
    const float* Wqkv = (const float*)d_in[1];
    const float* Wout = (const float*)d_in[2];
    float* out = (float*)d_out;

    float *qkv_p, *y_p, *xr_p, *w1_p, *w2_p;
    cudaGetSymbolAddress((void**)&qkv_p, g_qkv);
    cudaGetSymbolAddress((void**)&y_p,  g_y);
    cudaGetSymbolAddress((void**)&xr_p, g_xr);
    cudaGetSymbolAddress((void**)&w1_p, g_w1);
    cudaGetSymbolAddress((void**)&w2_p, g_w2);

    cudaFuncSetAttribute(gemm_tf32mma,
                         cudaFuncAttributeMaxDynamicSharedMemorySize, GEMM_SMEM);
    cudaFuncSetAttribute(fattn_kernel,
                         cudaFuncAttributeMaxDynamicSharedMemorySize, ATTN_SMEM);

    // 0) tf32-round GEMM inputs
    round_tf32_kernel<<<1184, 256>>>((const float4*)x,    (float4*)xr_p, MTOK * CDIM / 4);
    round_tf32_kernel<<<1184, 256>>>((const float4*)Wqkv, (float4*)w1_p, F3 * CDIM / 4);
    round_tf32_kernel<<<1184, 256>>>((const float4*)Wout, (float4*)w2_p, CDIM * CDIM / 4);

    // 1) qkv = x @ Wqkv^T
    gemm_tf32mma<<<dim3(F3 / BN, MTOK / BM), 256, GEMM_SMEM>>>(xr_p, w1_p, qkv_p, F3, CDIM);

    // 2) RoPE + split + V transpose
    rope_kernel<<<dim3(SEQ / 32, BATCH * NH), 128>>>();

    // 3) flash attention (tf32 mma) -> y
    fattn_kernel<<<dim3(SEQ / 64, BATCH * NH), 128, ATTN_SMEM>>>();

    // 4) out = y @ Wout^T
    gemm_tf32mma<<<dim3(CDIM / BN, MTOK / BM), 256, GEMM_SMEM>>>(y_p, w2_p, out, CDIM, CDIM);
}